// round 1
// baseline (speedup 1.0000x reference)
#include <cuda_runtime.h>
#include <cuda_bf16.h>

// cos(t_k/2), sin(t_k/2) for the 6 circuit parameters, computed by a tiny prep
// kernel (params live in device memory; no sync memcpy allowed).
__device__ float g_cs[12];

__global__ void qfe_prep(const float* __restrict__ tp) {
    int k = threadIdx.x;
    if (k < 6) {
        float s, c;
        sincosf(0.5f * tp[k], &s, &c);
        g_cs[2 * k]     = c;
        g_cs[2 * k + 1] = s;
    }
}

// Complex 2x2 rotation gates applied to an amplitude pair (r0+i*m0, r1+i*m1).
// Rx(t): [[c, -i s], [-i s, c]]
#define GATE_RX(r0, m0, r1, m1, C, S)                                   \
    {                                                                   \
        float tr0 = C * (r0) + S * (m1);                                \
        float tm0 = C * (m0) - S * (r1);                                \
        float tr1 = C * (r1) + S * (m0);                                \
        float tm1 = C * (m1) - S * (r0);                                \
        r0 = tr0; m0 = tm0; r1 = tr1; m1 = tm1;                         \
    }
// Ry(t): [[c, -s], [s, c]]  (real)
#define GATE_RY(r0, m0, r1, m1, C, S)                                   \
    {                                                                   \
        float tr0 = C * (r0) - S * (r1);                                \
        float tm0 = C * (m0) - S * (m1);                                \
        float tr1 = S * (r0) + C * (r1);                                \
        float tm1 = S * (m0) + C * (m1);                                \
        r0 = tr0; m0 = tm0; r1 = tr1; m1 = tm1;                         \
    }
// Rz(t): diag(e^{-it/2}, e^{+it/2})
#define GATE_RZ(r0, m0, r1, m1, C, S)                                   \
    {                                                                   \
        float tr0 = C * (r0) + S * (m0);                                \
        float tm0 = C * (m0) - S * (r0);                                \
        float tr1 = C * (r1) - S * (m1);                                \
        float tm1 = C * (m1) + S * (r1);                                \
        r0 = tr0; m0 = tm0; r1 = tr1; m1 = tm1;                         \
    }

// One thread per 2x2 patch. B=128, nh=nw=64 -> N = 524288 threads.
// The 4-qubit circuit factorizes exactly into pair (q0,q2) and pair (q1,q3):
// the only entanglers are CNOT(0->2) and CNOT(1->3), inputs are normalized,
// gates are unitary, so each <Z_w> is computed on its own 2-qubit system.
__global__ void __launch_bounds__(256) qfe_main(const float* __restrict__ x,
                                                float* __restrict__ out) {
    const int n = blockIdx.x * 256 + threadIdx.x;
    const int j = n & 63;
    const int i = (n >> 6) & 63;
    const int b = n >> 12;

    // x is (128, 1, 128, 128). Patch (b,i,j) covers rows 2i,2i+1, cols 2j,2j+1.
    // As float2: row stride = 64, batch stride = 8192. Fully coalesced in j.
    const float2* __restrict__ x2 = (const float2*)x;
    const int base = b * 8192 + i * 128 + j;
    const float2 rA = x2[base];        // a0 = x[b,2i,2j],   a1 = x[b,2i,2j+1]
    const float2 rB = x2[base + 64];   // a2 = x[b,2i+1,2j], a3 = x[b,2i+1,2j+1]

    float c0, s0, c1, s1, c2, s2, c3, s3;
    __sincosf(0.5f * rA.x, &s0, &c0);
    __sincosf(0.5f * rA.y, &s1, &c1);
    __sincosf(0.5f * rB.x, &s2, &c2);
    __sincosf(0.5f * rB.y, &s3, &c3);

    // Circuit params (uniform across all threads; L1 broadcast).
    const float C0 = g_cs[0],  S0 = g_cs[1];
    const float C1 = g_cs[2],  S1 = g_cs[3];
    const float C2 = g_cs[4],  S2 = g_cs[5];
    const float C3 = g_cs[6],  S3 = g_cs[7];
    const float C4 = g_cs[8],  S4 = g_cs[9];
    // t5 is a final Rz on q2: diagonal phase, provably cannot change |amp|^2.

    // ---------------- pair (q0, q2): index = q0*2 + q2 ----------------
    float vr0 = c0 * c2, vr1 = c0 * s2, vr2 = s0 * c2, vr3 = s0 * s2;
    float vi0 = 0.f, vi1 = 0.f, vi2 = 0.f, vi3 = 0.f;

    // Rx(t0) on q0 (stride 2)
    GATE_RX(vr0, vi0, vr2, vi2, C0, S0);
    GATE_RX(vr1, vi1, vr3, vi3, C0, S0);
    // Rz(t2) on q2 (stride 1)
    GATE_RZ(vr0, vi0, vr1, vi1, C2, S2);
    GATE_RZ(vr2, vi2, vr3, vi3, C2, S2);
    // CNOT(q0 -> q2): swap amps (q0=1,q2=0) <-> (q0=1,q2=1)
    { float tr = vr2; vr2 = vr3; vr3 = tr; float tm = vi2; vi2 = vi3; vi3 = tm; }
    // Ry(t4) on q0
    GATE_RY(vr0, vi0, vr2, vi2, C4, S4);
    GATE_RY(vr1, vi1, vr3, vi3, C4, S4);
    // (Rz(t5) on q2 dropped: diagonal, no effect on probabilities)

    const float p0 = vr0 * vr0 + vi0 * vi0;
    const float p1 = vr1 * vr1 + vi1 * vi1;
    const float p2 = vr2 * vr2 + vi2 * vi2;
    const float p3 = vr3 * vr3 + vi3 * vi3;
    const float m0 = (p0 + p1) - (p2 + p3);   // <Z_q0>
    const float m2 = (p0 - p1) + (p2 - p3);   // <Z_q2>

    // ---------------- pair (q1, q3): index = q1*2 + q3 ----------------
    float ur0 = c1 * c3, ur1 = c1 * s3, ur2 = s1 * c3, ur3 = s1 * s3;
    float ui0 = 0.f, ui1 = 0.f, ui2 = 0.f, ui3 = 0.f;

    // Ry(t1) on q1 (stride 2)
    GATE_RY(ur0, ui0, ur2, ui2, C1, S1);
    GATE_RY(ur1, ui1, ur3, ui3, C1, S1);
    // Rx(t3) on q3 (stride 1)
    GATE_RX(ur0, ui0, ur1, ui1, C3, S3);
    GATE_RX(ur2, ui2, ur3, ui3, C3, S3);
    // CNOT(q1 -> q3)
    { float tr = ur2; ur2 = ur3; ur3 = tr; float tm = ui2; ui2 = ui3; ui3 = tm; }

    const float q0p = ur0 * ur0 + ui0 * ui0;
    const float q1p = ur1 * ur1 + ui1 * ui1;
    const float q2p = ur2 * ur2 + ui2 * ui2;
    const float q3p = ur3 * ur3 + ui3 * ui3;
    const float m1 = (q0p + q1p) - (q2p + q3p);  // <Z_q1>
    const float m3 = (q0p - q1p) + (q2p - q3p);  // <Z_q3>

    // out[b, (i*64+j)*4 + w] -> float4 index == n. Fully coalesced.
    ((float4*)out)[n] = make_float4(m0, m1, m2, m3);
}

extern "C" void kernel_launch(void* const* d_in, const int* in_sizes, int n_in,
                              void* d_out, int out_size) {
    const float* x  = (const float*)d_in[0];
    const float* tp = (const float*)d_in[1];
    // Defensive against metadata ordering: layer_params has 6 elements.
    if (n_in >= 2 && in_sizes[0] == 6) {
        const float* t = x; x = tp; tp = t;
    }
    qfe_prep<<<1, 32>>>(tp);
    qfe_main<<<2048, 256>>>(x, (float*)d_out);
}

// round 3
// speedup vs baseline: 1.2605x; 1.2605x over previous
#include <cuda_runtime.h>
#include <cuda_bf16.h>

// QuantumFeatureExtractor — fully closed-form.
//
// The 4-qubit circuit factorizes into pairs (q0,q2) and (q1,q3); each <Z_w>
// reduces exactly to:
//   m0 = cos(t4)cos(t0)cos(a0) - sin(t4)cos(t2)sin(a0)sin(a2)
//   m1 = cos(a1 + t1)
//   m2 = cos(t0)cos(a0)cos(a2)
//   m3 = cos(a1 + t1) * cos(t3) * cos(a3)
// (final Rz(t5) is a diagonal phase: no effect on probabilities)
//
// One thread handles 2 patches (j = t and j = t+32 of the same warp-row) so
// all loads (float2) and stores (float4) are fully coalesced.

__device__ __forceinline__ float4 qfe_patch(float a0, float a1, float a2, float a3,
                                            float A, float Bc, float ct0, float ct3,
                                            float t1) {
    float s0, c0, s2, c2;
    __sincosf(a0, &s0, &c0);
    __sincosf(a2, &s2, &c2);
    const float m1 = __cosf(a1 + t1);
    const float c3 = __cosf(a3);
    const float m0 = fmaf(A, c0, -Bc * (s0 * s2));
    const float m2 = ct0 * c0 * c2;
    const float m3 = m1 * (ct3 * c3);
    return make_float4(m0, m1, m2, m3);
}

__global__ void __launch_bounds__(256) qfe_main(const float* __restrict__ x,
                                                const float* __restrict__ tp,
                                                float* __restrict__ out) {
    const int n = blockIdx.x * 256 + threadIdx.x;   // 262144 threads
    const int t = n & 31;        // lane -> j within warp-row
    const int w = n >> 5;        // global warp id = (b, i)
    const int i = w & 63;
    const int b = w >> 6;

    // Uniform circuit params: 5 MUFU per thread, L1-broadcast loads.
    const float t0 = tp[0], t1 = tp[1], t2 = tp[2], t3 = tp[3], t4 = tp[4];
    float st4, ct4;
    __sincosf(t4, &st4, &ct4);
    const float ct0 = __cosf(t0);
    const float ct2 = __cosf(t2);
    const float ct3 = __cosf(t3);
    const float A  = ct4 * ct0;   // cos t4 * cos t0
    const float Bc = st4 * ct2;   // sin t4 * cos t2

    // x is (128,1,128,128); patch (b,i,j) = rows 2i..2i+1, cols 2j..2j+1.
    // float2 view: row stride 64, batch stride 8192.
    const float2* __restrict__ x2 = (const float2*)x;
    const int base = b * 8192 + i * 128;

    // Patch 1: j = t
    const float2 rA1 = x2[base + t];
    const float2 rB1 = x2[base + 64 + t];
    // Patch 2: j = t + 32
    const float2 rA2 = x2[base + 32 + t];
    const float2 rB2 = x2[base + 96 + t];

    const float4 o1 = qfe_patch(rA1.x, rA1.y, rB1.x, rB1.y, A, Bc, ct0, ct3, t1);
    const float4 o2 = qfe_patch(rA2.x, rA2.y, rB2.x, rB2.y, A, Bc, ct0, ct3, t1);

    // out[b, (i*64+j)*4 + w] -> float4 index = b*4096 + i*64 + j.
    float4* __restrict__ out4 = (float4*)out;
    const int obase = w * 64;          // = b*4096 + i*64
    out4[obase + t]      = o1;         // coalesced
    out4[obase + 32 + t] = o2;         // coalesced
}

extern "C" void kernel_launch(void* const* d_in, const int* in_sizes, int n_in,
                              void* d_out, int out_size) {
    const float* x  = (const float*)d_in[0];
    const float* tp = (const float*)d_in[1];
    if (n_in >= 2 && in_sizes[0] == 6) {   // defensive vs metadata ordering
        const float* s = x; x = tp; tp = s;
    }
    qfe_main<<<1024, 256>>>(x, tp, (float*)d_out);
}